// round 1
// baseline (speedup 1.0000x reference)
#include <cuda_runtime.h>

// MeshGCN: 2-layer GCN, N=100000, FEAT=16, E=3.2M.
// out_l[d] = dinv[d] * ( hs_l[d] + sum_{(s,d) in E} hs_l[s] ) + b_l
//   where hs_l = (in_l @ W_l) * dinv,  dinv = rsqrt(indeg+1)
// Self-loop term is seeded into the accumulator; per-edge work is pure
// gather + red.global.add.v4.f32 (no per-edge FLOPs).

#define NMAX 100000
#define F 16

__device__ float  g_degf[NMAX];
__device__ float  g_dinv[NMAX];
__device__ float4 g_hs [NMAX * 4];
__device__ float4 g_agg[NMAX * 4];

__global__ __launch_bounds__(256) void k_deg_init(int n) {
    int i = blockIdx.x * 256 + threadIdx.x;
    if (i < n) g_degf[i] = 1.0f;  // self-loop
}

__global__ __launch_bounds__(256) void k_deg_accum(const int* __restrict__ dst, int E) {
    int e = blockIdx.x * 256 + threadIdx.x;
    if (e < E) atomicAdd(&g_degf[dst[e]], 1.0f);
}

// hs = (x @ W1) * dinv ; agg = hs (self-loop seed) ; dinv stored
__global__ __launch_bounds__(256) void k_pre1(const float* __restrict__ x,
                                              const float* __restrict__ W, int n) {
    __shared__ float sW[256];
    int tid = threadIdx.x;
    sW[tid] = W[tid];
    __syncthreads();
    int i = blockIdx.x * 256 + tid;
    if (i >= n) return;

    const float4* xp = reinterpret_cast<const float4*>(x) + (size_t)i * 4;
    float xr[16];
#pragma unroll
    for (int c = 0; c < 4; c++) {
        float4 t = xp[c];
        xr[c * 4 + 0] = t.x; xr[c * 4 + 1] = t.y;
        xr[c * 4 + 2] = t.z; xr[c * 4 + 3] = t.w;
    }
    float acc[16];
#pragma unroll
    for (int j = 0; j < 16; j++) acc[j] = 0.0f;
#pragma unroll
    for (int k = 0; k < 16; k++) {
        float xk = xr[k];
#pragma unroll
        for (int j = 0; j < 16; j++) acc[j] += xk * sW[k * 16 + j];
    }
    float dv = rsqrtf(g_degf[i]);
    g_dinv[i] = dv;
#pragma unroll
    for (int c = 0; c < 4; c++) {
        float4 o;
        o.x = acc[c * 4 + 0] * dv; o.y = acc[c * 4 + 1] * dv;
        o.z = acc[c * 4 + 2] * dv; o.w = acc[c * 4 + 3] * dv;
        g_hs [i * 4 + c] = o;
        g_agg[i * 4 + c] = o;
    }
}

// 4 threads per edge; each thread gathers one float4 of hs[src] and
// vector-reduces it into agg[dst]. Gathers are 64B-contiguous per edge.
__global__ __launch_bounds__(256) void k_scatter(const int* __restrict__ src,
                                                 const int* __restrict__ dst, int E) {
    int t = blockIdx.x * 256 + threadIdx.x;
    int e = t >> 2;
    if (e >= E) return;
    int c = t & 3;
    int s = src[e];
    int d = dst[e];
    float4 v = __ldg(&g_hs[(size_t)s * 4 + c]);
    float* ap = reinterpret_cast<float*>(&g_agg[(size_t)d * 4 + c]);
    asm volatile("red.global.add.v4.f32 [%0], {%1, %2, %3, %4};"
                 :: "l"(ap), "f"(v.x), "f"(v.y), "f"(v.z), "f"(v.w)
                 : "memory");
}

// y = relu(dinv*agg + b1) ; hs = (y @ W2) * dinv ; agg = hs
__global__ __launch_bounds__(256) void k_mid(const float* __restrict__ W2,
                                             const float* __restrict__ b1, int n) {
    __shared__ float sW[256];
    __shared__ float sb[16];
    int tid = threadIdx.x;
    sW[tid] = W2[tid];
    if (tid < 16) sb[tid] = b1[tid];
    __syncthreads();
    int i = blockIdx.x * 256 + tid;
    if (i >= n) return;

    float dv = g_dinv[i];
    float y[16];
#pragma unroll
    for (int c = 0; c < 4; c++) {
        float4 a = g_agg[i * 4 + c];
        float v0 = a.x * dv + sb[c * 4 + 0];
        float v1 = a.y * dv + sb[c * 4 + 1];
        float v2 = a.z * dv + sb[c * 4 + 2];
        float v3 = a.w * dv + sb[c * 4 + 3];
        y[c * 4 + 0] = v0 > 0.0f ? v0 : 0.0f;
        y[c * 4 + 1] = v1 > 0.0f ? v1 : 0.0f;
        y[c * 4 + 2] = v2 > 0.0f ? v2 : 0.0f;
        y[c * 4 + 3] = v3 > 0.0f ? v3 : 0.0f;
    }
    float acc[16];
#pragma unroll
    for (int j = 0; j < 16; j++) acc[j] = 0.0f;
#pragma unroll
    for (int k = 0; k < 16; k++) {
        float yk = y[k];
#pragma unroll
        for (int j = 0; j < 16; j++) acc[j] += yk * sW[k * 16 + j];
    }
#pragma unroll
    for (int c = 0; c < 4; c++) {
        float4 o;
        o.x = acc[c * 4 + 0] * dv; o.y = acc[c * 4 + 1] * dv;
        o.z = acc[c * 4 + 2] * dv; o.w = acc[c * 4 + 3] * dv;
        g_hs [i * 4 + c] = o;
        g_agg[i * 4 + c] = o;
    }
}

// out = dinv*agg + b2
__global__ __launch_bounds__(256) void k_final(const float* __restrict__ b2,
                                               float* __restrict__ out, int n) {
    __shared__ float sb[16];
    int tid = threadIdx.x;
    if (tid < 16) sb[tid] = b2[tid];
    __syncthreads();
    int i = blockIdx.x * 256 + tid;
    if (i >= n) return;

    float dv = g_dinv[i];
    float4* op = reinterpret_cast<float4*>(out) + (size_t)i * 4;
#pragma unroll
    for (int c = 0; c < 4; c++) {
        float4 a = g_agg[i * 4 + c];
        float4 o;
        o.x = a.x * dv + sb[c * 4 + 0];
        o.y = a.y * dv + sb[c * 4 + 1];
        o.z = a.z * dv + sb[c * 4 + 2];
        o.w = a.w * dv + sb[c * 4 + 3];
        op[c] = o;
    }
}

extern "C" void kernel_launch(void* const* d_in, const int* in_sizes, int n_in,
                              void* d_out, int out_size) {
    const float* x  = (const float*)d_in[0];
    const int*   ei = (const int*)  d_in[1];
    const float* W1 = (const float*)d_in[2];
    const float* b1 = (const float*)d_in[3];
    const float* W2 = (const float*)d_in[4];
    const float* b2 = (const float*)d_in[5];
    float* out = (float*)d_out;

    int E = in_sizes[1] / 2;
    int n = in_sizes[0] / F;
    const int* src = ei;
    const int* dst = ei + E;

    int nb_n = (n + 255) / 256;
    int nb_e = (E + 255) / 256;
    int nb_s = (E * 4 + 255) / 256;

    k_deg_init <<<nb_n, 256>>>(n);
    k_deg_accum<<<nb_e, 256>>>(dst, E);
    k_pre1     <<<nb_n, 256>>>(x, W1, n);
    k_scatter  <<<nb_s, 256>>>(src, dst, E);
    k_mid      <<<nb_n, 256>>>(W2, b1, n);
    k_scatter  <<<nb_s, 256>>>(src, dst, E);
    k_final    <<<nb_n, 256>>>(b2, out, n);
}